// round 4
// baseline (speedup 1.0000x reference)
#include <cuda_runtime.h>
#include <cuda_bf16.h>
#include <cstdint>

// Problem constants (FiBiNet): B=1024, F=32, D=64, g=2
static constexpr int Bn   = 1024;
static constexpr int Pn   = 496;
static constexpr int KP   = 512;    // padded K for outgemm
static constexpr int EMB  = 2048;   // F*D
static constexpr int OUTN = 512;
static constexpr int OROW = 2560;   // EMB + OUTN

// Scratch (static __device__: allocation-guard safe)
__device__ __nv_bfloat16 g_dTh[Bn * KP];    // dots hi, [b][p] row-major, p padded
__device__ __nv_bfloat16 g_dTl[Bn * KP];    // dots lo
__device__ __nv_bfloat16 g_WoTh[OUTN * KP]; // Wo^T hi, [n][k]
__device__ __nv_bfloat16 g_WoTl[OUTN * KP]; // Wo^T lo
__device__ float g_a1[Bn * 32];

// ---------------------------------------------------------------------------
// HMMA: D(16x8,f32) += A(16x16,bf16 row) x B(16x8,bf16 col)
// ---------------------------------------------------------------------------
__device__ __forceinline__ void mma16816(float* d, const uint32_t* a, const uint32_t* b) {
    asm volatile(
        "mma.sync.aligned.m16n8k16.row.col.f32.bf16.bf16.f32 "
        "{%0,%1,%2,%3}, {%4,%5,%6,%7}, {%8,%9}, {%0,%1,%2,%3};"
        : "+f"(d[0]), "+f"(d[1]), "+f"(d[2]), "+f"(d[3])
        : "r"(a[0]), "r"(a[1]), "r"(a[2]), "r"(a[3]), "r"(b[0]), "r"(b[1]));
}

// ---------------------------------------------------------------------------
// Kernel A: a1 = relu(z @ W1 + b1). 8 warps/block, 1 batch row per warp.
// ---------------------------------------------------------------------------
__global__ __launch_bounds__(256) void senet_a1_kernel(
    const float* __restrict__ x, const float* __restrict__ W1, const float* __restrict__ b1)
{
    __shared__ float sW1[128 * 32];
    __shared__ float sz[8][128];

    const int t = threadIdx.x, w = t >> 5, lane = t & 31;
    const int row = blockIdx.x * 8 + w;

    #pragma unroll
    for (int r = 0; r < 4; r++)
        ((float4*)sW1)[t + 256 * r] = ((const float4*)W1)[t + 256 * r];
    __syncthreads();

    const float* xrow = x + (size_t)row * EMB;
    #pragma unroll
    for (int half = 0; half < 2; half++) {
        const int s = lane + 32 * half;
        const float* base = xrow + s * 32;
        float mx = -1e30f, sm = 0.f;
        #pragma unroll
        for (int it = 0; it < 8; it++) {
            float4 v = *(const float4*)(base + it * 4);
            mx = fmaxf(mx, fmaxf(fmaxf(v.x, v.y), fmaxf(v.z, v.w)));
            sm += v.x + v.y + v.z + v.w;
        }
        const int f = s >> 1, gi = s & 1;
        sz[w][f * 4 + gi]     = mx;
        sz[w][f * 4 + 2 + gi] = sm * (1.0f / 32.0f);
    }
    __syncwarp();

    float acc = b1[lane];
    #pragma unroll 8
    for (int k = 0; k < 128; k++) acc += sz[w][k] * sW1[k * 32 + lane];
    g_a1[row * 32 + lane] = fmaxf(acc, 0.0f);
}

// ---------------------------------------------------------------------------
// Kernel B: weights = a1@W2+b2; senet = x*(1+w); LayerNorm -> out[:,0:2048]
// ---------------------------------------------------------------------------
__global__ __launch_bounds__(256) void senet_ln_kernel(
    const float* __restrict__ x, const float* __restrict__ W2, const float* __restrict__ b2,
    const float* __restrict__ ln_s, const float* __restrict__ ln_b, float* __restrict__ out)
{
    __shared__ float sa1[8 * 32];
    __shared__ float wsum[8][8], wsq[8][8];
    __shared__ float mu_s[8], rs_s[8];

    const int t = threadIdx.x;
    const int row0 = blockIdx.x * 8;

    sa1[t] = g_a1[row0 * 32 + t];
    __syncthreads();

    float acc[8][8];
    #pragma unroll
    for (int c = 0; c < 8; c++)
        #pragma unroll
        for (int r = 0; r < 8; r++) acc[c][r] = 0.f;

    #pragma unroll 4
    for (int k = 0; k < 32; k++) {
        float w2v[8], a1v[8];
        #pragma unroll
        for (int c = 0; c < 8; c++) w2v[c] = W2[k * EMB + t + 256 * c];
        #pragma unroll
        for (int r = 0; r < 8; r++) a1v[r] = sa1[r * 32 + k];
        #pragma unroll
        for (int c = 0; c < 8; c++)
            #pragma unroll
            for (int r = 0; r < 8; r++) acc[c][r] += a1v[r] * w2v[c];
    }

    float sum[8], sq[8];
    #pragma unroll
    for (int r = 0; r < 8; r++) { sum[r] = 0.f; sq[r] = 0.f; }
    #pragma unroll
    for (int c = 0; c < 8; c++) {
        const int j = t + 256 * c;
        const float b2v = b2[j];
        #pragma unroll
        for (int r = 0; r < 8; r++) {
            float xv = x[(size_t)(row0 + r) * EMB + j];
            float s = xv * (1.0f + b2v + acc[c][r]);
            acc[c][r] = s;
            sum[r] += s;
            sq[r]  += s * s;
        }
    }
    const int w = t >> 5, lane = t & 31;
    #pragma unroll
    for (int r = 0; r < 8; r++) {
        float a = sum[r], b = sq[r];
        #pragma unroll
        for (int off = 16; off; off >>= 1) {
            a += __shfl_xor_sync(0xffffffffu, a, off);
            b += __shfl_xor_sync(0xffffffffu, b, off);
        }
        if (lane == 0) { wsum[w][r] = a; wsq[w][r] = b; }
    }
    __syncthreads();
    if (t < 8) {
        float a = 0.f, b = 0.f;
        #pragma unroll
        for (int ww = 0; ww < 8; ww++) { a += wsum[ww][t]; b += wsq[ww][t]; }
        const float mu = a * (1.0f / EMB);
        mu_s[t] = mu;
        rs_s[t] = rsqrtf(b * (1.0f / EMB) - mu * mu + 1e-6f);
    }
    __syncthreads();

    #pragma unroll
    for (int c = 0; c < 8; c++) {
        const int j = t + 256 * c;
        const float lsv = ln_s[j], lbv = ln_b[j];
        #pragma unroll
        for (int r = 0; r < 8; r++)
            out[(size_t)(row0 + r) * OROW + j] = (acc[c][r] - mu_s[r]) * rs_s[r] * lsv + lbv;
    }
}

// ---------------------------------------------------------------------------
// Kernel C: Wo (496x512 f32) -> Wo^T [n][k] bf16 hi/lo, k padded to 512.
// ---------------------------------------------------------------------------
__global__ __launch_bounds__(256) void wo_prep_kernel(const float* __restrict__ Wo)
{
    __shared__ float s[32][33];
    const int t = threadIdx.x;
    const int k0 = blockIdx.x * 32, n0 = blockIdx.y * 32;

    #pragma unroll
    for (int it = 0; it < 4; it++) {
        const int idx = t + 256 * it;
        const int a = idx >> 5, b = idx & 31;   // a: k, b: n
        s[a][b] = (k0 + a < Pn) ? Wo[(size_t)(k0 + a) * OUTN + n0 + b] : 0.f;
    }
    __syncthreads();
    #pragma unroll
    for (int it = 0; it < 4; it++) {
        const int idx = t + 256 * it;
        const int n = idx >> 5, kk = idx & 31;
        const float v = s[kk][n];
        const __nv_bfloat16 h = __float2bfloat16(v);
        g_WoTh[(size_t)(n0 + n) * KP + k0 + kk] = h;
        g_WoTl[(size_t)(n0 + n) * KP + k0 + kk] = __float2bfloat16(v - __bfloat162float(h));
    }
}

// ---------------------------------------------------------------------------
// Kernel 2: pairwise bilinear dots via HMMA bf16 split-precision.
// Block = (pair p, 128-batch tile), 128 threads / 4 warps, 32 rows per warp.
// dots -> bf16 hi/lo at g_dT[b][p].
// ---------------------------------------------------------------------------
static constexpr int XPAD = 72;
static constexpr int WPAD = 72;
static constexpr int JPAD = 68;

static constexpr int SM_XH = 0;                        // bf16 element offsets
static constexpr int SM_XL = SM_XH + 128 * XPAD;
static constexpr int SM_WH = SM_XL + 128 * XPAD;
static constexpr int SM_WL = SM_WH + 64 * WPAD;
static constexpr int SM_END_BF16 = SM_WL + 64 * WPAD;
static constexpr int SM_XJ_BYTES = SM_END_BF16 * 2;
static constexpr int SM_BP_BYTES = SM_XJ_BYTES + 128 * JPAD * 4;
static constexpr int PAIR_SMEM   = SM_BP_BYTES + 64 * 4;

__global__ __launch_bounds__(128) void pair_mma_kernel(
    const float* __restrict__ x, const float* __restrict__ Wp, const float* __restrict__ bp)
{
    extern __shared__ char smem[];
    __nv_bfloat16* sXh = (__nv_bfloat16*)smem;
    __nv_bfloat16* sXl = sXh + SM_XL;
    __nv_bfloat16* sWh = sXh + SM_WH;
    __nv_bfloat16* sWl = sXh + SM_WL;
    float* sXj = (float*)(smem + SM_XJ_BYTES);
    float* sbp = (float*)(smem + SM_BP_BYTES);

    const int t = threadIdx.x, wid = t >> 5, lane = t & 31;
    const int p = blockIdx.x;
    const int b0 = blockIdx.y * 128;

    // pair p -> (i, j)
    int i = 0, rem = p;
    while (rem >= 31 - i) { rem -= 31 - i; ++i; }
    const int j = i + 1 + rem;

    if (t < 64) sbp[t] = bp[p * 64 + t];

    // zero dT pad columns (done by p==0 blocks, once per batch tile)
    if (p == 0) {
        #pragma unroll
        for (int it = 0; it < 16; it++) {
            const int idx = t + 128 * it;       // 128 rows x 16 pad cols
            const int row = idx >> 4, cc = idx & 15;
            g_dTh[(size_t)(b0 + row) * KP + Pn + cc] = __float2bfloat16(0.f);
            g_dTl[(size_t)(b0 + row) * KP + Pn + cc] = __float2bfloat16(0.f);
        }
    }

    // Wp[p] (64x64, d-major) -> sW[e][d] bf16 hi/lo
    #pragma unroll
    for (int it = 0; it < 8; it++) {
        const int idx = t + 128 * it;
        const int d = idx >> 4, e4 = (idx & 15) * 4;
        const float4 v = *(const float4*)(Wp + (size_t)p * 4096 + d * 64 + e4);
        const float vv[4] = {v.x, v.y, v.z, v.w};
        #pragma unroll
        for (int q = 0; q < 4; q++) {
            const __nv_bfloat16 h = __float2bfloat16(vv[q]);
            sWh[(e4 + q) * WPAD + d] = h;
            sWl[(e4 + q) * WPAD + d] = __float2bfloat16(vv[q] - __bfloat162float(h));
        }
    }

    // xi tile (128x64) -> bf16 hi/lo; xj tile -> f32
    #pragma unroll
    for (int it = 0; it < 16; it++) {
        const int idx = t + 128 * it;
        const int row = idx >> 4, ch = idx & 15;
        const float4 v = *(const float4*)(x + (size_t)(b0 + row) * EMB + i * 64 + ch * 4);
        __nv_bfloat16 h0 = __float2bfloat16(v.x), h1 = __float2bfloat16(v.y);
        __nv_bfloat16 h2 = __float2bfloat16(v.z), h3 = __float2bfloat16(v.w);
        __nv_bfloat162 hA = __halves2bfloat162(h0, h1), hB = __halves2bfloat162(h2, h3);
        __nv_bfloat162 lA = __halves2bfloat162(__float2bfloat16(v.x - __bfloat162float(h0)),
                                               __float2bfloat16(v.y - __bfloat162float(h1)));
        __nv_bfloat162 lB = __halves2bfloat162(__float2bfloat16(v.z - __bfloat162float(h2)),
                                               __float2bfloat16(v.w - __bfloat162float(h3)));
        uint2 hp, lp;
        hp.x = *(uint32_t*)&hA; hp.y = *(uint32_t*)&hB;
        lp.x = *(uint32_t*)&lA; lp.y = *(uint32_t*)&lB;
        *(uint2*)(sXh + row * XPAD + ch * 4) = hp;
        *(uint2*)(sXl + row * XPAD + ch * 4) = lp;

        const float4 vj = *(const float4*)(x + (size_t)(b0 + row) * EMB + j * 64 + ch * 4);
        *(float4*)(sXj + row * JPAD + ch * 4) = vj;
    }
    __syncthreads();

    // MMA mainloop: warp owns 32 rows (two m16 subtiles)
    const int r = lane >> 2, kq = (lane & 3) * 2;
    const int m0 = wid * 32;

    float acc[2][8][4];
    #pragma unroll
    for (int mt = 0; mt < 2; mt++)
        #pragma unroll
        for (int nt = 0; nt < 8; nt++)
            #pragma unroll
            for (int q = 0; q < 4; q++) acc[mt][nt][q] = 0.f;

    #pragma unroll
    for (int kt = 0; kt < 4; kt++) {
        const int kb = kt * 16 + kq;
        uint32_t ah[2][4], al[2][4];
        #pragma unroll
        for (int mt = 0; mt < 2; mt++) {
            const int rb = m0 + mt * 16 + r;
            ah[mt][0] = *(const uint32_t*)(sXh + rb * XPAD + kb);
            ah[mt][1] = *(const uint32_t*)(sXh + (rb + 8) * XPAD + kb);
            ah[mt][2] = *(const uint32_t*)(sXh + rb * XPAD + kb + 8);
            ah[mt][3] = *(const uint32_t*)(sXh + (rb + 8) * XPAD + kb + 8);
            al[mt][0] = *(const uint32_t*)(sXl + rb * XPAD + kb);
            al[mt][1] = *(const uint32_t*)(sXl + (rb + 8) * XPAD + kb);
            al[mt][2] = *(const uint32_t*)(sXl + rb * XPAD + kb + 8);
            al[mt][3] = *(const uint32_t*)(sXl + (rb + 8) * XPAD + kb + 8);
        }
        #pragma unroll
        for (int nt = 0; nt < 8; nt++) {
            const int nrow = nt * 8 + r;
            uint32_t bh[2], bl[2];
            bh[0] = *(const uint32_t*)(sWh + nrow * WPAD + kb);
            bh[1] = *(const uint32_t*)(sWh + nrow * WPAD + kb + 8);
            bl[0] = *(const uint32_t*)(sWl + nrow * WPAD + kb);
            bl[1] = *(const uint32_t*)(sWl + nrow * WPAD + kb + 8);
            mma16816(acc[0][nt], ah[0], bh);
            mma16816(acc[0][nt], ah[0], bl);
            mma16816(acc[0][nt], al[0], bh);
            mma16816(acc[1][nt], ah[1], bh);
            mma16816(acc[1][nt], ah[1], bl);
            mma16816(acc[1][nt], al[1], bh);
        }
    }

    // epilogue: dots = sum_e (proj + bp) * xj; quad reduce; bf16 split store
    #pragma unroll
    for (int mt = 0; mt < 2; mt++) {
        const int rb = m0 + mt * 16 + r;
        float dot0 = 0.f, dot1 = 0.f;
        #pragma unroll
        for (int nt = 0; nt < 8; nt++) {
            const int c0 = nt * 8 + (lane & 3) * 2;
            const float bp0 = sbp[c0], bp1 = sbp[c0 + 1];
            const float2 xj0 = *(const float2*)(sXj + rb * JPAD + c0);
            const float2 xj1 = *(const float2*)(sXj + (rb + 8) * JPAD + c0);
            dot0 += (acc[mt][nt][0] + bp0) * xj0.x + (acc[mt][nt][1] + bp1) * xj0.y;
            dot1 += (acc[mt][nt][2] + bp0) * xj1.x + (acc[mt][nt][3] + bp1) * xj1.y;
        }
        dot0 += __shfl_xor_sync(0xffffffffu, dot0, 1);
        dot0 += __shfl_xor_sync(0xffffffffu, dot0, 2);
        dot1 += __shfl_xor_sync(0xffffffffu, dot1, 1);
        dot1 += __shfl_xor_sync(0xffffffffu, dot1, 2);
        if ((lane & 3) == 0) {
            const __nv_bfloat16 h0 = __float2bfloat16(dot0);
            const __nv_bfloat16 h1 = __float2bfloat16(dot1);
            const size_t o0 = (size_t)(b0 + rb) * KP + p;
            const size_t o1 = (size_t)(b0 + rb + 8) * KP + p;
            g_dTh[o0] = h0;
            g_dTl[o0] = __float2bfloat16(dot0 - __bfloat162float(h0));
            g_dTh[o1] = h1;
            g_dTl[o1] = __float2bfloat16(dot1 - __bfloat162float(h1));
        }
    }
}

// ---------------------------------------------------------------------------
// Kernel 3: bilinear = dots @ Wo + bo via HMMA bf16 split -> out[:, 2048:2560]
// A = g_dT [m=b][k=p] hi/lo, B = g_WoT [n][k] hi/lo. M=1024, N=512, K=512pad.
// 64x64 tiles, 256 thr, warp = 16m x 32n. 8 k-stages of 64.
// ---------------------------------------------------------------------------
__global__ __launch_bounds__(256) void outgemm_mma_kernel(
    const float* __restrict__ bo, float* __restrict__ out)
{
    __shared__ __nv_bfloat16 sAh[64 * 72], sAl[64 * 72];
    __shared__ __nv_bfloat16 sBh[64 * 72], sBl[64 * 72];

    const int t = threadIdx.x, wid = t >> 5, lane = t & 31;
    const int n0 = blockIdx.x * 64, m0 = blockIdx.y * 64;
    const int mwid = wid & 3, nwid = wid >> 2;
    const int r = lane >> 2, kq = (lane & 3) * 2;

    float acc[4][4];
    #pragma unroll
    for (int nt = 0; nt < 4; nt++)
        #pragma unroll
        for (int q = 0; q < 4; q++) acc[nt][q] = 0.f;

    for (int s = 0; s < 8; s++) {
        const int k0 = s * 64;
        __syncthreads();
        #pragma unroll
        for (int it = 0; it < 2; it++) {
            const int idx = t + 256 * it;
            const int row = idx >> 3, ch = idx & 7;
            *(uint4*)(sAh + row * 72 + ch * 8) =
                *(const uint4*)(g_dTh + (size_t)(m0 + row) * KP + k0 + ch * 8);
            *(uint4*)(sAl + row * 72 + ch * 8) =
                *(const uint4*)(g_dTl + (size_t)(m0 + row) * KP + k0 + ch * 8);
            *(uint4*)(sBh + row * 72 + ch * 8) =
                *(const uint4*)(g_WoTh + (size_t)(n0 + row) * KP + k0 + ch * 8);
            *(uint4*)(sBl + row * 72 + ch * 8) =
                *(const uint4*)(g_WoTl + (size_t)(n0 + row) * KP + k0 + ch * 8);
        }
        __syncthreads();

        #pragma unroll
        for (int kt = 0; kt < 4; kt++) {
            const int kb = kt * 16 + kq;
            const int rb = mwid * 16 + r;
            uint32_t ah[4], al[4];
            ah[0] = *(const uint32_t*)(sAh + rb * 72 + kb);
            ah[1] = *(const uint32_t*)(sAh + (rb + 8) * 72 + kb);
            ah[2] = *(const uint32_t*)(sAh + rb * 72 + kb + 8);
            ah[3] = *(const uint32_t*)(sAh + (rb + 8) * 72 + kb + 8);
            al[0] = *(const uint32_t*)(sAl + rb * 72 + kb);
            al[1] = *(const uint32_t*)(sAl + (rb + 8) * 72 + kb);
            al[2] = *(const uint32_t*)(sAl + rb * 72 + kb + 8);
            al[3] = *(const uint32_t*)(sAl + (rb + 8) * 72 + kb + 8);
            #pragma unroll
            for (int nt = 0; nt < 4; nt++) {
                const int nrow = nwid * 32 + nt * 8 + r;
                uint32_t bh[2], bl[2];
                bh[0] = *(const uint32_t*)(sBh + nrow * 72 + kb);
                bh[1] = *(const uint32_t*)(sBh + nrow * 72 + kb + 8);
                bl[0] = *(const uint32_t*)(sBl + nrow * 72 + kb);
                bl[1] = *(const uint32_t*)(sBl + nrow * 72 + kb + 8);
                mma16816(acc[nt], ah, bh);
                mma16816(acc[nt], ah, bl);
                mma16816(acc[nt], al, bh);
            }
        }
    }

    // epilogue
    #pragma unroll
    for (int nt = 0; nt < 4; nt++) {
        const int c = n0 + nwid * 32 + nt * 8 + (lane & 3) * 2;
        const float bo0 = bo[c], bo1 = bo[c + 1];
        const int mrow = m0 + mwid * 16 + r;
        float2 v0 = {acc[nt][0] + bo0, acc[nt][1] + bo1};
        float2 v1 = {acc[nt][2] + bo0, acc[nt][3] + bo1};
        *(float2*)(out + (size_t)mrow * OROW + EMB + c) = v0;
        *(float2*)(out + (size_t)(mrow + 8) * OROW + EMB + c) = v1;
    }
}

// ---------------------------------------------------------------------------
extern "C" void kernel_launch(void* const* d_in, const int* in_sizes, int n_in,
                              void* d_out, int out_size)
{
    const float* x    = (const float*)d_in[0];
    const float* W1   = (const float*)d_in[1];
    const float* b1   = (const float*)d_in[2];
    const float* W2   = (const float*)d_in[3];
    const float* b2   = (const float*)d_in[4];
    const float* ln_s = (const float*)d_in[5];
    const float* ln_b = (const float*)d_in[6];
    const float* Wp   = (const float*)d_in[7];
    const float* bp   = (const float*)d_in[8];
    const float* Wo   = (const float*)d_in[9];
    const float* bo   = (const float*)d_in[10];
    float* out = (float*)d_out;

    cudaFuncSetAttribute(pair_mma_kernel, cudaFuncAttributeMaxDynamicSharedMemorySize, PAIR_SMEM);

    wo_prep_kernel<<<dim3(16, 16), 256>>>(Wo);
    senet_a1_kernel<<<Bn / 8, 256>>>(x, W1, b1);
    senet_ln_kernel<<<Bn / 8, 256>>>(x, W2, b2, ln_s, ln_b, out);
    pair_mma_kernel<<<dim3(Pn, Bn / 128), 128, PAIR_SMEM>>>(x, Wp, bp);
    outgemm_mma_kernel<<<dim3(OUTN / 64, Bn / 64), 256>>>(bo, out);
}

// round 5
// speedup vs baseline: 1.2996x; 1.2996x over previous
#include <cuda_runtime.h>
#include <cuda_bf16.h>
#include <cstdint>

// Problem constants (FiBiNet): B=1024, F=32, D=64, g=2
static constexpr int Bn   = 1024;
static constexpr int Pn   = 496;
static constexpr int KP   = 512;    // padded K for outgemm
static constexpr int EMB  = 2048;   // F*D
static constexpr int OUTN = 512;
static constexpr int OROW = 2560;   // EMB + OUTN

// Scratch (static __device__: allocation-guard safe)
__device__ __nv_bfloat16 g_xh[Bn * EMB];     // x hi
__device__ __nv_bfloat16 g_xl[Bn * EMB];     // x lo
__device__ __nv_bfloat16 g_WpTh[Pn * 4096];  // Wp^T hi, [p][e][d]
__device__ __nv_bfloat16 g_WpTl[Pn * 4096];  // Wp^T lo
__device__ __nv_bfloat16 g_dTh[Bn * KP];     // dots hi, [b][p], p padded
__device__ __nv_bfloat16 g_dTl[Bn * KP];     // dots lo
__device__ __nv_bfloat16 g_WoTh[OUTN * KP];  // Wo^T hi, [n][k]
__device__ __nv_bfloat16 g_WoTl[OUTN * KP];  // Wo^T lo
__device__ float g_a1[Bn * 32];

// ---------------------------------------------------------------------------
// HMMA: D(16x8,f32) += A(16x16,bf16 row) x B(16x8,bf16 col)
// ---------------------------------------------------------------------------
__device__ __forceinline__ void mma16816(float* d, const uint32_t* a, const uint32_t* b) {
    asm volatile(
        "mma.sync.aligned.m16n8k16.row.col.f32.bf16.bf16.f32 "
        "{%0,%1,%2,%3}, {%4,%5,%6,%7}, {%8,%9}, {%0,%1,%2,%3};"
        : "+f"(d[0]), "+f"(d[1]), "+f"(d[2]), "+f"(d[3])
        : "r"(a[0]), "r"(a[1]), "r"(a[2]), "r"(a[3]), "r"(b[0]), "r"(b[1]));
}

__device__ __forceinline__ void split_bf16(float v, __nv_bfloat16& h, __nv_bfloat16& l) {
    h = __float2bfloat16(v);
    l = __float2bfloat16(v - __bfloat162float(h));
}

// ---------------------------------------------------------------------------
// Prep: x -> bf16 hi/lo (one float4 per thread)
// ---------------------------------------------------------------------------
__global__ __launch_bounds__(256) void xprep_kernel(const float* __restrict__ x)
{
    const int idx = blockIdx.x * 256 + threadIdx.x;   // float4 index
    const float4 v = ((const float4*)x)[idx];
    __nv_bfloat16 h[4], l[4];
    split_bf16(v.x, h[0], l[0]);
    split_bf16(v.y, h[1], l[1]);
    split_bf16(v.z, h[2], l[2]);
    split_bf16(v.w, h[3], l[3]);
    *(uint2*)(g_xh + (size_t)idx * 4) = *(uint2*)h;
    *(uint2*)(g_xl + (size_t)idx * 4) = *(uint2*)l;
}

// ---------------------------------------------------------------------------
// Prep: Wp[p] (64x64 [d][e]) -> [p][e][d] bf16 hi/lo. One block per pair.
// ---------------------------------------------------------------------------
__global__ __launch_bounds__(256) void wp_prep_kernel(const float* __restrict__ Wp)
{
    __shared__ float s[64 * 65];
    const int t = threadIdx.x, p = blockIdx.x;

    #pragma unroll
    for (int it = 0; it < 4; it++) {
        const int idx = t + 256 * it;
        const int d = idx >> 4, e4 = (idx & 15) * 4;
        const float4 v = *(const float4*)(Wp + (size_t)p * 4096 + d * 64 + e4);
        s[(e4 + 0) * 65 + d] = v.x;
        s[(e4 + 1) * 65 + d] = v.y;
        s[(e4 + 2) * 65 + d] = v.z;
        s[(e4 + 3) * 65 + d] = v.w;
    }
    __syncthreads();
    #pragma unroll
    for (int it = 0; it < 16; it++) {
        const int idx = t + 256 * it;
        const int e = idx >> 6, d = idx & 63;
        __nv_bfloat16 h, l;
        split_bf16(s[e * 65 + d], h, l);
        g_WpTh[(size_t)p * 4096 + idx] = h;
        g_WpTl[(size_t)p * 4096 + idx] = l;
    }
}

// ---------------------------------------------------------------------------
// Prep: Wo (496x512 f32) -> Wo^T [n][k] bf16 hi/lo, k padded to 512.
// ---------------------------------------------------------------------------
__global__ __launch_bounds__(256) void wo_prep_kernel(const float* __restrict__ Wo)
{
    __shared__ float s[32][33];
    const int t = threadIdx.x;
    const int k0 = blockIdx.x * 32, n0 = blockIdx.y * 32;

    #pragma unroll
    for (int it = 0; it < 4; it++) {
        const int idx = t + 256 * it;
        const int a = idx >> 5, b = idx & 31;
        s[a][b] = (k0 + a < Pn) ? Wo[(size_t)(k0 + a) * OUTN + n0 + b] : 0.f;
    }
    __syncthreads();
    #pragma unroll
    for (int it = 0; it < 4; it++) {
        const int idx = t + 256 * it;
        const int n = idx >> 5, kk = idx & 31;
        __nv_bfloat16 h, l;
        split_bf16(s[kk][n], h, l);
        g_WoTh[(size_t)(n0 + n) * KP + k0 + kk] = h;
        g_WoTl[(size_t)(n0 + n) * KP + k0 + kk] = l;
    }
}

// ---------------------------------------------------------------------------
// Kernel A: a1 = relu(z @ W1 + b1). 8 warps/block, 1 batch row per warp.
// ---------------------------------------------------------------------------
__global__ __launch_bounds__(256) void senet_a1_kernel(
    const float* __restrict__ x, const float* __restrict__ W1, const float* __restrict__ b1)
{
    __shared__ float sW1[128 * 32];
    __shared__ float sz[8][128];

    const int t = threadIdx.x, w = t >> 5, lane = t & 31;
    const int row = blockIdx.x * 8 + w;

    #pragma unroll
    for (int r = 0; r < 4; r++)
        ((float4*)sW1)[t + 256 * r] = ((const float4*)W1)[t + 256 * r];
    __syncthreads();

    const float* xrow = x + (size_t)row * EMB;
    #pragma unroll
    for (int half = 0; half < 2; half++) {
        const int s = lane + 32 * half;
        const float* base = xrow + s * 32;
        float mx = -1e30f, sm = 0.f;
        #pragma unroll
        for (int it = 0; it < 8; it++) {
            float4 v = *(const float4*)(base + it * 4);
            mx = fmaxf(mx, fmaxf(fmaxf(v.x, v.y), fmaxf(v.z, v.w)));
            sm += v.x + v.y + v.z + v.w;
        }
        const int f = s >> 1, gi = s & 1;
        sz[w][f * 4 + gi]     = mx;
        sz[w][f * 4 + 2 + gi] = sm * (1.0f / 32.0f);
    }
    __syncwarp();

    float acc = b1[lane];
    #pragma unroll 8
    for (int k = 0; k < 128; k++) acc += sz[w][k] * sW1[k * 32 + lane];
    g_a1[row * 32 + lane] = fmaxf(acc, 0.0f);
}

// ---------------------------------------------------------------------------
// Kernel B: weights = a1@W2+b2; senet = x*(1+w); LayerNorm -> out[:,0:2048]
// ---------------------------------------------------------------------------
__global__ __launch_bounds__(256) void senet_ln_kernel(
    const float* __restrict__ x, const float* __restrict__ W2, const float* __restrict__ b2,
    const float* __restrict__ ln_s, const float* __restrict__ ln_b, float* __restrict__ out)
{
    __shared__ float sa1[8 * 32];
    __shared__ float wsum[8][8], wsq[8][8];
    __shared__ float mu_s[8], rs_s[8];

    const int t = threadIdx.x;
    const int row0 = blockIdx.x * 8;

    sa1[t] = g_a1[row0 * 32 + t];
    __syncthreads();

    float acc[8][8];
    #pragma unroll
    for (int c = 0; c < 8; c++)
        #pragma unroll
        for (int r = 0; r < 8; r++) acc[c][r] = 0.f;

    #pragma unroll 4
    for (int k = 0; k < 32; k++) {
        float w2v[8], a1v[8];
        #pragma unroll
        for (int c = 0; c < 8; c++) w2v[c] = W2[k * EMB + t + 256 * c];
        #pragma unroll
        for (int r = 0; r < 8; r++) a1v[r] = sa1[r * 32 + k];
        #pragma unroll
        for (int c = 0; c < 8; c++)
            #pragma unroll
            for (int r = 0; r < 8; r++) acc[c][r] += a1v[r] * w2v[c];
    }

    float sum[8], sq[8];
    #pragma unroll
    for (int r = 0; r < 8; r++) { sum[r] = 0.f; sq[r] = 0.f; }
    #pragma unroll
    for (int c = 0; c < 8; c++) {
        const int j = t + 256 * c;
        const float b2v = b2[j];
        #pragma unroll
        for (int r = 0; r < 8; r++) {
            float xv = x[(size_t)(row0 + r) * EMB + j];
            float s = xv * (1.0f + b2v + acc[c][r]);
            acc[c][r] = s;
            sum[r] += s;
            sq[r]  += s * s;
        }
    }
    const int w = t >> 5, lane = t & 31;
    #pragma unroll
    for (int r = 0; r < 8; r++) {
        float a = sum[r], b = sq[r];
        #pragma unroll
        for (int off = 16; off; off >>= 1) {
            a += __shfl_xor_sync(0xffffffffu, a, off);
            b += __shfl_xor_sync(0xffffffffu, b, off);
        }
        if (lane == 0) { wsum[w][r] = a; wsq[w][r] = b; }
    }
    __syncthreads();
    if (t < 8) {
        float a = 0.f, b = 0.f;
        #pragma unroll
        for (int ww = 0; ww < 8; ww++) { a += wsum[ww][t]; b += wsq[ww][t]; }
        const float mu = a * (1.0f / EMB);
        mu_s[t] = mu;
        rs_s[t] = rsqrtf(b * (1.0f / EMB) - mu * mu + 1e-6f);
    }
    __syncthreads();

    #pragma unroll
    for (int c = 0; c < 8; c++) {
        const int j = t + 256 * c;
        const float lsv = ln_s[j], lbv = ln_b[j];
        #pragma unroll
        for (int r = 0; r < 8; r++)
            out[(size_t)(row0 + r) * OROW + j] = (acc[c][r] - mu_s[r]) * rs_s[r] * lsv + lbv;
    }
}

// ---------------------------------------------------------------------------
// Kernel 2: pairwise bilinear dots via HMMA bf16 split-precision.
// Block = (pair p, 128-batch tile), 256 threads / 8 warps, 16 rows per warp.
// All operands pre-converted bf16; staging is pure 16B copies. ~55KB smem
// -> 4 CTAs/SM. Epilogue reads xj (f32) straight from global (L2-resident).
// ---------------------------------------------------------------------------
static constexpr int XPAD = 72;
static constexpr int WPAD = 72;

static constexpr int SM_XL = 128 * XPAD;               // bf16 element offsets
static constexpr int SM_WH = 2 * 128 * XPAD;
static constexpr int SM_WL = SM_WH + 64 * WPAD;
static constexpr int SM_END_BF16 = SM_WL + 64 * WPAD;
static constexpr int SM_BP_BYTES = SM_END_BF16 * 2;
static constexpr int PAIR_SMEM   = SM_BP_BYTES + 64 * 4;

__global__ __launch_bounds__(256) void pair_mma_kernel(
    const float* __restrict__ x, const float* __restrict__ bp)
{
    extern __shared__ char smem[];
    __nv_bfloat16* sXh = (__nv_bfloat16*)smem;
    __nv_bfloat16* sXl = sXh + SM_XL;
    __nv_bfloat16* sWh = sXh + SM_WH;
    __nv_bfloat16* sWl = sXh + SM_WL;
    float* sbp = (float*)(smem + SM_BP_BYTES);

    const int t = threadIdx.x, wid = t >> 5, lane = t & 31;
    const int p = blockIdx.x;
    const int b0 = blockIdx.y * 128;

    // pair p -> (i, j)
    int i = 0, rem = p;
    while (rem >= 31 - i) { rem -= 31 - i; ++i; }
    const int j = i + 1 + rem;

    if (t < 64) sbp[t] = bp[p * 64 + t];

    // zero dT pad columns (p==0 blocks only)
    if (p == 0) {
        #pragma unroll
        for (int it = 0; it < 8; it++) {
            const int idx = t + 256 * it;       // 128 rows x 16 pad cols
            const int row = idx >> 4, cc = idx & 15;
            g_dTh[(size_t)(b0 + row) * KP + Pn + cc] = __float2bfloat16(0.f);
            g_dTl[(size_t)(b0 + row) * KP + Pn + cc] = __float2bfloat16(0.f);
        }
    }

    // stage W^T hi/lo (64 rows x 64 bf16 = 512 uint4 each)
    #pragma unroll
    for (int it = 0; it < 2; it++) {
        const int idx = t + 256 * it;
        const int row = idx >> 3, ch = idx & 7;
        *(uint4*)(sWh + row * WPAD + ch * 8) =
            *(const uint4*)(g_WpTh + (size_t)p * 4096 + row * 64 + ch * 8);
        *(uint4*)(sWl + row * WPAD + ch * 8) =
            *(const uint4*)(g_WpTl + (size_t)p * 4096 + row * 64 + ch * 8);
    }
    // stage xi hi/lo (128 rows x 64 bf16 = 1024 uint4 each)
    #pragma unroll
    for (int it = 0; it < 4; it++) {
        const int idx = t + 256 * it;
        const int row = idx >> 3, ch = idx & 7;
        *(uint4*)(sXh + row * XPAD + ch * 8) =
            *(const uint4*)(g_xh + (size_t)(b0 + row) * EMB + i * 64 + ch * 8);
        *(uint4*)(sXl + row * XPAD + ch * 8) =
            *(const uint4*)(g_xl + (size_t)(b0 + row) * EMB + i * 64 + ch * 8);
    }
    __syncthreads();

    // MMA mainloop: warp owns 16 rows
    const int r = lane >> 2, kq = (lane & 3) * 2;
    const int m0 = wid * 16;

    uint32_t ah[4][4], al[4][4];
    #pragma unroll
    for (int kt = 0; kt < 4; kt++) {
        const int kb = kt * 16 + kq;
        ah[kt][0] = *(const uint32_t*)(sXh + (m0 + r) * XPAD + kb);
        ah[kt][1] = *(const uint32_t*)(sXh + (m0 + r + 8) * XPAD + kb);
        ah[kt][2] = *(const uint32_t*)(sXh + (m0 + r) * XPAD + kb + 8);
        ah[kt][3] = *(const uint32_t*)(sXh + (m0 + r + 8) * XPAD + kb + 8);
        al[kt][0] = *(const uint32_t*)(sXl + (m0 + r) * XPAD + kb);
        al[kt][1] = *(const uint32_t*)(sXl + (m0 + r + 8) * XPAD + kb);
        al[kt][2] = *(const uint32_t*)(sXl + (m0 + r) * XPAD + kb + 8);
        al[kt][3] = *(const uint32_t*)(sXl + (m0 + r + 8) * XPAD + kb + 8);
    }

    float acc[8][4];
    #pragma unroll
    for (int nt = 0; nt < 8; nt++)
        #pragma unroll
        for (int q = 0; q < 4; q++) acc[nt][q] = 0.f;

    #pragma unroll
    for (int nt = 0; nt < 8; nt++) {
        const int nrow = nt * 8 + r;
        #pragma unroll
        for (int kt = 0; kt < 4; kt++) {
            const int kb = kt * 16 + kq;
            uint32_t bh[2], bl[2];
            bh[0] = *(const uint32_t*)(sWh + nrow * WPAD + kb);
            bh[1] = *(const uint32_t*)(sWh + nrow * WPAD + kb + 8);
            bl[0] = *(const uint32_t*)(sWl + nrow * WPAD + kb);
            bl[1] = *(const uint32_t*)(sWl + nrow * WPAD + kb + 8);
            mma16816(acc[nt], ah[kt], bh);
            mma16816(acc[nt], ah[kt], bl);
            mma16816(acc[nt], al[kt], bh);
        }
    }

    // epilogue: dots = sum_e (proj + bp) * xj (xj from global, L2-resident)
    const float* xj0p = x + (size_t)(b0 + m0 + r) * EMB + j * 64;
    const float* xj1p = x + (size_t)(b0 + m0 + r + 8) * EMB + j * 64;
    float dot0 = 0.f, dot1 = 0.f;
    #pragma unroll
    for (int nt = 0; nt < 8; nt++) {
        const int c0 = nt * 8 + (lane & 3) * 2;
        const float bp0 = sbp[c0], bp1 = sbp[c0 + 1];
        const float2 xj0 = *(const float2*)(xj0p + c0);
        const float2 xj1 = *(const float2*)(xj1p + c0);
        dot0 += (acc[nt][0] + bp0) * xj0.x + (acc[nt][1] + bp1) * xj0.y;
        dot1 += (acc[nt][2] + bp0) * xj1.x + (acc[nt][3] + bp1) * xj1.y;
    }
    dot0 += __shfl_xor_sync(0xffffffffu, dot0, 1);
    dot0 += __shfl_xor_sync(0xffffffffu, dot0, 2);
    dot1 += __shfl_xor_sync(0xffffffffu, dot1, 1);
    dot1 += __shfl_xor_sync(0xffffffffu, dot1, 2);
    if ((lane & 3) == 0) {
        __nv_bfloat16 h0, l0, h1, l1;
        split_bf16(dot0, h0, l0);
        split_bf16(dot1, h1, l1);
        const size_t o0 = (size_t)(b0 + m0 + r) * KP + p;
        const size_t o1 = (size_t)(b0 + m0 + r + 8) * KP + p;
        g_dTh[o0] = h0; g_dTl[o0] = l0;
        g_dTh[o1] = h1; g_dTl[o1] = l1;
    }
}

// ---------------------------------------------------------------------------
// Kernel 3: bilinear = dots @ Wo + bo via HMMA bf16 split -> out[:, 2048:2560]
// ---------------------------------------------------------------------------
__global__ __launch_bounds__(256) void outgemm_mma_kernel(
    const float* __restrict__ bo, float* __restrict__ out)
{
    __shared__ __nv_bfloat16 sAh[64 * 72], sAl[64 * 72];
    __shared__ __nv_bfloat16 sBh[64 * 72], sBl[64 * 72];

    const int t = threadIdx.x, wid = t >> 5, lane = t & 31;
    const int n0 = blockIdx.x * 64, m0 = blockIdx.y * 64;
    const int mwid = wid & 3, nwid = wid >> 2;
    const int r = lane >> 2, kq = (lane & 3) * 2;

    float acc[4][4];
    #pragma unroll
    for (int nt = 0; nt < 4; nt++)
        #pragma unroll
        for (int q = 0; q < 4; q++) acc[nt][q] = 0.f;

    for (int s = 0; s < 8; s++) {
        const int k0 = s * 64;
        __syncthreads();
        #pragma unroll
        for (int it = 0; it < 2; it++) {
            const int idx = t + 256 * it;
            const int row = idx >> 3, ch = idx & 7;
            *(uint4*)(sAh + row * 72 + ch * 8) =
                *(const uint4*)(g_dTh + (size_t)(m0 + row) * KP + k0 + ch * 8);
            *(uint4*)(sAl + row * 72 + ch * 8) =
                *(const uint4*)(g_dTl + (size_t)(m0 + row) * KP + k0 + ch * 8);
            *(uint4*)(sBh + row * 72 + ch * 8) =
                *(const uint4*)(g_WoTh + (size_t)(n0 + row) * KP + k0 + ch * 8);
            *(uint4*)(sBl + row * 72 + ch * 8) =
                *(const uint4*)(g_WoTl + (size_t)(n0 + row) * KP + k0 + ch * 8);
        }
        __syncthreads();

        #pragma unroll
        for (int kt = 0; kt < 4; kt++) {
            const int kb = kt * 16 + kq;
            const int rb = mwid * 16 + r;
            uint32_t ah[4], al[4];
            ah[0] = *(const uint32_t*)(sAh + rb * 72 + kb);
            ah[1] = *(const uint32_t*)(sAh + (rb + 8) * 72 + kb);
            ah[2] = *(const uint32_t*)(sAh + rb * 72 + kb + 8);
            ah[3] = *(const uint32_t*)(sAh + (rb + 8) * 72 + kb + 8);
            al[0] = *(const uint32_t*)(sAl + rb * 72 + kb);
            al[1] = *(const uint32_t*)(sAl + (rb + 8) * 72 + kb);
            al[2] = *(const uint32_t*)(sAl + rb * 72 + kb + 8);
            al[3] = *(const uint32_t*)(sAl + (rb + 8) * 72 + kb + 8);
            #pragma unroll
            for (int nt = 0; nt < 4; nt++) {
                const int nrow = nwid * 32 + nt * 8 + r;
                uint32_t bh[2], bl[2];
                bh[0] = *(const uint32_t*)(sBh + nrow * 72 + kb);
                bh[1] = *(const uint32_t*)(sBh + nrow * 72 + kb + 8);
                bl[0] = *(const uint32_t*)(sBl + nrow * 72 + kb);
                bl[1] = *(const uint32_t*)(sBl + nrow * 72 + kb + 8);
                mma16816(acc[nt], ah, bh);
                mma16816(acc[nt], ah, bl);
                mma16816(acc[nt], al, bh);
            }
        }
    }

    #pragma unroll
    for (int nt = 0; nt < 4; nt++) {
        const int c = n0 + nwid * 32 + nt * 8 + (lane & 3) * 2;
        const float bo0 = bo[c], bo1 = bo[c + 1];
        const int mrow = m0 + mwid * 16 + r;
        float2 v0 = {acc[nt][0] + bo0, acc[nt][1] + bo1};
        float2 v1 = {acc[nt][2] + bo0, acc[nt][3] + bo1};
        *(float2*)(out + (size_t)mrow * OROW + EMB + c) = v0;
        *(float2*)(out + (size_t)(mrow + 8) * OROW + EMB + c) = v1;
    }
}

// ---------------------------------------------------------------------------
extern "C" void kernel_launch(void* const* d_in, const int* in_sizes, int n_in,
                              void* d_out, int out_size)
{
    const float* x    = (const float*)d_in[0];
    const float* W1   = (const float*)d_in[1];
    const float* b1   = (const float*)d_in[2];
    const float* W2   = (const float*)d_in[3];
    const float* b2   = (const float*)d_in[4];
    const float* ln_s = (const float*)d_in[5];
    const float* ln_b = (const float*)d_in[6];
    const float* Wp   = (const float*)d_in[7];
    const float* bp   = (const float*)d_in[8];
    const float* Wo   = (const float*)d_in[9];
    const float* bo   = (const float*)d_in[10];
    float* out = (float*)d_out;

    cudaFuncSetAttribute(pair_mma_kernel, cudaFuncAttributeMaxDynamicSharedMemorySize, PAIR_SMEM);

    xprep_kernel<<<Bn * EMB / 4 / 256, 256>>>(x);
    wp_prep_kernel<<<Pn, 256>>>(Wp);
    wo_prep_kernel<<<dim3(16, 16), 256>>>(Wo);
    senet_a1_kernel<<<Bn / 8, 256>>>(x, W1, b1);
    senet_ln_kernel<<<Bn / 8, 256>>>(x, W2, b2, ln_s, ln_b, out);
    pair_mma_kernel<<<dim3(Pn, Bn / 128), 256, PAIR_SMEM>>>(x, bp);
    outgemm_mma_kernel<<<dim3(OUTN / 64, Bn / 64), 256>>>(bo, out);
}